// round 2
// baseline (speedup 1.0000x reference)
#include <cuda_runtime.h>
#include <cstdint>

// Problem constants
#define NIMG   128          // images per input
#define NTOT   256          // stacked rows (a then b)
#define CCH    16           // channels
#define HP     16           // pooled H
#define WP     16           // pooled W
#define DDIM   4096         // CCH*HP*WP
#define TILE   32           // pair tile edge
#define NTROW  8            // NTOT/TILE
#define NTILES 36           // upper-tri tiles: 8*9/2
#define DCHUNK 256          // d per block (pair kernel)
#define NDCH   16           // DDIM/DCHUNK
#define DSTEP  32           // smem staging depth

// Scratch: pooled mean/variance, TRANSPOSED layout [d][n] (n contiguous).
__device__ float g_Mt[DDIM * NTOT];
__device__ float g_Vt[DDIM * NTOT];
__device__ double g_acc;

__device__ __forceinline__ float ex2_approx(float x) {
    float y; asm("ex2.approx.ftz.f32 %0, %1;" : "=f"(y) : "f"(x)); return y;
}
__device__ __forceinline__ float rsqrt_approx(float x) {
    float y; asm("rsqrt.approx.ftz.f32 %0, %1;" : "=f"(y) : "f"(x)); return y;
}

__global__ void zero_acc_kernel() { g_acc = 0.0; }

// ---------------------------------------------------------------------------
// Pooling: one block per (ph, c, array). 256 threads.
// arrays: 0=mu_a->Mt[:,0:128], 1=logvar_a->Vt[:,0:128],
//         2=mu_b->Mt[:,128:256], 3=logvar_b->Vt[:,128:256]
// Reads coalesced over pw, smem transpose, writes coalesced over n.
// ---------------------------------------------------------------------------
__global__ __launch_bounds__(256) void pool_kernel(
    const float* __restrict__ mu_a, const float* __restrict__ lv_a,
    const float* __restrict__ mu_b, const float* __restrict__ lv_b)
{
    const int ph  = blockIdx.x;      // 0..15
    const int c   = blockIdx.y;      // 0..15
    const int arr = blockIdx.z;      // 0..3
    const int tid = threadIdx.x;

    const float* src = (arr == 0) ? mu_a : (arr == 1) ? lv_a : (arr == 2) ? mu_b : lv_b;
    float* dst       = (arr & 1) ? g_Vt : g_Mt;
    const int n_off  = (arr < 2) ? 0 : NIMG;
    const bool isVar = (arr & 1);

    __shared__ float s[NIMG * 17];   // padded transpose buffer (n*17 + pw)

    const float2* src2 = reinterpret_cast<const float2*>(src);

    // read + pool: o = n*16 + pw
    #pragma unroll
    for (int k = 0; k < 8; k++) {
        int o  = tid + 256 * k;      // 0..2047
        int n  = o >> 4;
        int pw = o & 15;
        // base float index: n*16384 + c*1024 + ph*64 + 2*pw  -> /2 for float2
        int i2 = n * 8192 + c * 512 + ph * 32 + pw;
        float2 r0 = src2[i2];
        float2 r1 = src2[i2 + 16];   // next h row (+32 floats)
        float p;
        if (isVar) {
            p = (__expf(r0.x) + __expf(r0.y) + __expf(r1.x) + __expf(r1.y)) * 0.0625f;
        } else {
            p = (r0.x + r0.y + r1.x + r1.y) * 0.25f;
        }
        s[n * 17 + pw] = p;
    }
    __syncthreads();

    // write: o = pw*128 + n ; dst index = ((c*16+ph)*16+pw)*256 + n_off + n
    const int dbase = ((c * 16 + ph) * 16) * NTOT + n_off;
    #pragma unroll
    for (int k = 0; k < 8; k++) {
        int o  = tid + 256 * k;
        int pw = o >> 7;
        int n  = o & 127;
        dst[dbase + pw * NTOT + n] = s[n * 17 + pw];
    }
}

// ---------------------------------------------------------------------------
// Pair kernel: grid (36 upper-tri tiles, 16 d-chunks), 256 threads.
// Each thread owns a 2x2 pair micro-tile; smem stages DSTEP d-slices of
// M/V for both tile rows.
// ---------------------------------------------------------------------------
__global__ __launch_bounds__(256) void pair_kernel()
{
    // decode upper-triangular tile index -> (ti, tj), ti <= tj
    int rem = blockIdx.x;
    int ti = 0;
    while (rem >= NTROW - ti) { rem -= NTROW - ti; ti++; }
    const int tj = ti + rem;

    const int i0 = ti * TILE;
    const int j0 = tj * TILE;
    const int d0 = blockIdx.y * DCHUNK;

    const int tid  = threadIdx.x;
    const int jx   = tid & 15;       // j micro-col (pairs of 2)
    const int iy   = tid >> 4;       // i micro-row (pairs of 2)

    __shared__ float sMi[DSTEP * TILE];
    __shared__ float sVi[DSTEP * TILE];
    __shared__ float sMj[DSTEP * TILE];
    __shared__ float sVj[DSTEP * TILE];
    __shared__ float warpsum[8];

    float acc00 = 0.f, acc01 = 0.f, acc10 = 0.f, acc11 = 0.f;

    const int ln = tid & 31;         // load lane -> n within tile
    const int lr = tid >> 5;         // load row base (8 rows of d)

    const float c_exp = -0.72134752044448170367f;  // -0.5*log2(e)

    for (int ds = 0; ds < DCHUNK; ds += DSTEP) {
        __syncthreads();
        #pragma unroll
        for (int k = 0; k < DSTEP; k += 8) {
            int dd = lr + k;
            int g  = (d0 + ds + dd) * NTOT;
            sMi[dd * TILE + ln] = g_Mt[g + i0 + ln];
            sVi[dd * TILE + ln] = g_Vt[g + i0 + ln];
            sMj[dd * TILE + ln] = g_Mt[g + j0 + ln];
            sVj[dd * TILE + ln] = g_Vt[g + j0 + ln];
        }
        __syncthreads();

        #pragma unroll 4
        for (int dd = 0; dd < DSTEP; dd++) {
            float2 mi = *reinterpret_cast<float2*>(&sMi[dd * TILE + 2 * iy]);
            float2 vi = *reinterpret_cast<float2*>(&sVi[dd * TILE + 2 * iy]);
            float2 mj = *reinterpret_cast<float2*>(&sMj[dd * TILE + 2 * jx]);
            float2 vj = *reinterpret_cast<float2*>(&sVj[dd * TILE + 2 * jx]);

            {
                float d = mi.x - mj.x, sv = vi.x + vj.x;
                float r = rsqrt_approx(sv);
                float t = d * r;
                acc00 += ex2_approx(t * t * c_exp) * r;
            }
            {
                float d = mi.x - mj.y, sv = vi.x + vj.y;
                float r = rsqrt_approx(sv);
                float t = d * r;
                acc01 += ex2_approx(t * t * c_exp) * r;
            }
            {
                float d = mi.y - mj.x, sv = vi.y + vj.x;
                float r = rsqrt_approx(sv);
                float t = d * r;
                acc10 += ex2_approx(t * t * c_exp) * r;
            }
            {
                float d = mi.y - mj.y, sv = vi.y + vj.y;
                float r = rsqrt_approx(sv);
                float t = d * r;
                acc11 += ex2_approx(t * t * c_exp) * r;
            }
        }
    }

    // block reduce
    float v = (acc00 + acc01) + (acc10 + acc11);
    #pragma unroll
    for (int o = 16; o; o >>= 1) v += __shfl_xor_sync(0xffffffffu, v, o);
    if ((tid & 31) == 0) warpsum[tid >> 5] = v;
    __syncthreads();
    if (tid == 0) {
        float b = 0.f;
        #pragma unroll
        for (int k = 0; k < 8; k++) b += warpsum[k];
        // weight: sign product (a=+1, b=-1) and x2 for off-diagonal tiles
        double sgn = ((ti < 4) == (tj < 4)) ? 1.0 : -1.0;
        double w   = (ti == tj) ? sgn : 2.0 * sgn;
        atomicAdd(&g_acc, (double)b * w);
    }
}

__global__ void finalize_kernel(float* out) { out[0] = (float)g_acc; }

extern "C" void kernel_launch(void* const* d_in, const int* in_sizes, int n_in,
                              void* d_out, int out_size)
{
    const float* mu_a = (const float*)d_in[0];
    const float* lv_a = (const float*)d_in[1];
    const float* mu_b = (const float*)d_in[2];
    const float* lv_b = (const float*)d_in[3];
    float* out = (float*)d_out;

    zero_acc_kernel<<<1, 1>>>();
    pool_kernel<<<dim3(HP, CCH, 4), 256>>>(mu_a, lv_a, mu_b, lv_b);
    pair_kernel<<<dim3(NTILES, NDCH), 256>>>();
    finalize_kernel<<<1, 1>>>(out);
}

// round 5
// speedup vs baseline: 1.0887x; 1.0887x over previous
#include <cuda_runtime.h>
#include <cuda_fp16.h>
#include <cstdint>

// Problem constants
#define NIMG   128          // images per input
#define NTOT   256          // stacked rows (a then b)
#define CCH    16           // channels
#define HP     16           // pooled H
#define WP     16           // pooled W
#define DDIM   4096         // CCH*HP*WP
#define TILE   32           // pair tile edge
#define NTROW  8            // NTOT/TILE
#define NTILES 36           // upper-tri tiles: 8*9/2
#define DCHUNK 256          // d per block (pair kernel)
#define NDCH   16           // DDIM/DCHUNK
#define DSTEP  32           // smem staging depth
#define NBLK_TOTAL (NTILES * NDCH)   // 576

// sqrt(0.5*log2(e)) folded into the pooled means so the inner loop needs no
// extra constant multiply: term = ex2(-(d'*r)^2) * r with d' = d*sqrt(k).
#define SQRT_K      0.8493218003f
#define MEAN_SCALE  (0.25f * SQRT_K)   // avgpool /4 fused with sqrt(k)

// Scratch: pooled mean/variance, TRANSPOSED layout [d][n] (n contiguous).
__device__ float g_Mt[DDIM * NTOT];
__device__ float g_Vt[DDIM * NTOT];
__device__ double g_acc;          // zero-init; reset by last block each run
__device__ unsigned int g_done;   // zero-init; reset by last block each run

__device__ __forceinline__ float rsqrt_approx(float x) {
    float y; asm("rsqrt.approx.ftz.f32 %0, %1;" : "=f"(y) : "f"(x)); return y;
}
__device__ __forceinline__ __half2 h2ex2(__half2 x) {
    unsigned xi = *reinterpret_cast<unsigned*>(&x), yi;
    asm("ex2.approx.f16x2 %0, %1;" : "=r"(yi) : "r"(xi));
    return *reinterpret_cast<__half2*>(&yi);
}

// ---------------------------------------------------------------------------
// Pooling: one block per (ph, c, array). 256 threads.
// arrays: 0=mu_a->Mt[:,0:128], 1=logvar_a->Vt[:,0:128],
//         2=mu_b->Mt[:,128:256], 3=logvar_b->Vt[:,128:256]
// Means are additionally scaled by sqrt(0.5*log2 e).
// ---------------------------------------------------------------------------
__global__ __launch_bounds__(256) void pool_kernel(
    const float* __restrict__ mu_a, const float* __restrict__ lv_a,
    const float* __restrict__ mu_b, const float* __restrict__ lv_b)
{
    const int ph  = blockIdx.x;      // 0..15
    const int c   = blockIdx.y;      // 0..15
    const int arr = blockIdx.z;      // 0..3
    const int tid = threadIdx.x;

    const float* src = (arr == 0) ? mu_a : (arr == 1) ? lv_a : (arr == 2) ? mu_b : lv_b;
    float* dst       = (arr & 1) ? g_Vt : g_Mt;
    const int n_off  = (arr < 2) ? 0 : NIMG;
    const bool isVar = (arr & 1);

    __shared__ float s[NIMG * 17];   // padded transpose buffer (n*17 + pw)

    const float2* src2 = reinterpret_cast<const float2*>(src);

    #pragma unroll
    for (int k = 0; k < 8; k++) {
        int o  = tid + 256 * k;      // 0..2047
        int n  = o >> 4;
        int pw = o & 15;
        int i2 = n * 8192 + c * 512 + ph * 32 + pw;
        float2 r0 = src2[i2];
        float2 r1 = src2[i2 + 16];
        float p;
        if (isVar) {
            p = (__expf(r0.x) + __expf(r0.y) + __expf(r1.x) + __expf(r1.y)) * 0.0625f;
        } else {
            p = (r0.x + r0.y + r1.x + r1.y) * MEAN_SCALE;
        }
        s[n * 17 + pw] = p;
    }
    __syncthreads();

    const int dbase = ((c * 16 + ph) * 16) * NTOT + n_off;
    #pragma unroll
    for (int k = 0; k < 8; k++) {
        int o  = tid + 256 * k;
        int pw = o >> 7;
        int n  = o & 127;
        dst[dbase + pw * NTOT + n] = s[n * 17 + pw];
    }
}

// ---------------------------------------------------------------------------
// Pair kernel: grid (36 upper-tri tiles, 16 d-chunks), 256 threads.
// 2x2 pair micro-tile per thread; ex2 done as f16x2 (2 terms / MUFU op);
// e*r accumulated with HFMA2 into half2, flushed to f32 every DSTEP iters.
// ---------------------------------------------------------------------------
__global__ __launch_bounds__(256) void pair_kernel(float* __restrict__ out)
{
    int rem = blockIdx.x;
    int ti = 0;
    while (rem >= NTROW - ti) { rem -= NTROW - ti; ti++; }
    const int tj = ti + rem;

    const int i0 = ti * TILE;
    const int j0 = tj * TILE;
    const int d0 = blockIdx.y * DCHUNK;

    const int tid  = threadIdx.x;
    const int jx   = tid & 15;       // j micro-col (pairs of 2)
    const int iy   = tid >> 4;       // i micro-row (pairs of 2)

    __shared__ float sMi[DSTEP * TILE];
    __shared__ float sVi[DSTEP * TILE];
    __shared__ float sMj[DSTEP * TILE];
    __shared__ float sVj[DSTEP * TILE];
    __shared__ float warpsum[8];

    float facc0 = 0.f, facc1 = 0.f;

    const int ln = tid & 31;         // load lane -> n within tile
    const int lr = tid >> 5;         // load row base (8 rows of d)

    for (int ds = 0; ds < DCHUNK; ds += DSTEP) {
        __syncthreads();
        #pragma unroll
        for (int k = 0; k < DSTEP; k += 8) {
            int dd = lr + k;
            int g  = (d0 + ds + dd) * NTOT;
            sMi[dd * TILE + ln] = g_Mt[g + i0 + ln];
            sVi[dd * TILE + ln] = g_Vt[g + i0 + ln];
            sMj[dd * TILE + ln] = g_Mt[g + j0 + ln];
            sVj[dd * TILE + ln] = g_Vt[g + j0 + ln];
        }
        __syncthreads();

        __half2 hacc0 = __floats2half2_rn(0.f, 0.f);
        __half2 hacc1 = __floats2half2_rn(0.f, 0.f);

        #pragma unroll 4
        for (int dd = 0; dd < DSTEP; dd++) {
            float2 mi = *reinterpret_cast<float2*>(&sMi[dd * TILE + 2 * iy]);
            float2 vi = *reinterpret_cast<float2*>(&sVi[dd * TILE + 2 * iy]);
            float2 mj = *reinterpret_cast<float2*>(&sMj[dd * TILE + 2 * jx]);
            float2 vj = *reinterpret_cast<float2*>(&sVj[dd * TILE + 2 * jx]);

            // row 0 (mi.x, vi.x) against j-pair
            {
                float s0 = vi.x + vj.x, s1 = vi.x + vj.y;
                float r0 = rsqrt_approx(s0), r1 = rsqrt_approx(s1);
                float t0 = (mi.x - mj.x) * r0;
                float t1 = (mi.x - mj.y) * r1;
                __half2 u  = __floats2half2_rn(-t0 * t0, -t1 * t1);
                __half2 rh = __floats2half2_rn(r0, r1);
                hacc0 = __hfma2(h2ex2(u), rh, hacc0);
            }
            // row 1 (mi.y, vi.y) against j-pair
            {
                float s0 = vi.y + vj.x, s1 = vi.y + vj.y;
                float r0 = rsqrt_approx(s0), r1 = rsqrt_approx(s1);
                float t0 = (mi.y - mj.x) * r0;
                float t1 = (mi.y - mj.y) * r1;
                __half2 u  = __floats2half2_rn(-t0 * t0, -t1 * t1);
                __half2 rh = __floats2half2_rn(r0, r1);
                hacc1 = __hfma2(h2ex2(u), rh, hacc1);
            }
        }

        // flush half2 accumulators to f32 (32 adds max per half -> safe range)
        facc0 += __low2float(hacc0) + __high2float(hacc0);
        facc1 += __low2float(hacc1) + __high2float(hacc1);
    }

    // block reduce
    float v = facc0 + facc1;
    #pragma unroll
    for (int o = 16; o; o >>= 1) v += __shfl_xor_sync(0xffffffffu, v, o);
    if ((tid & 31) == 0) warpsum[tid >> 5] = v;
    __syncthreads();
    if (tid == 0) {
        float b = 0.f;
        #pragma unroll
        for (int k = 0; k < 8; k++) b += warpsum[k];
        double sgn = ((ti < 4) == (tj < 4)) ? 1.0 : -1.0;
        double w   = (ti == tj) ? sgn : 2.0 * sgn;
        atomicAdd(&g_acc, (double)b * w);
        __threadfence();
        unsigned n = atomicAdd(&g_done, 1u);
        if (n == NBLK_TOTAL - 1) {
            __threadfence();
            double total = *((volatile double*)&g_acc);
            out[0] = (float)total;
            // reset for the next (graph-replayed) run
            *((volatile double*)&g_acc) = 0.0;
            *((volatile unsigned*)&g_done) = 0u;
            __threadfence();
        }
    }
}

extern "C" void kernel_launch(void* const* d_in, const int* in_sizes, int n_in,
                              void* d_out, int out_size)
{
    const float* mu_a = (const float*)d_in[0];
    const float* lv_a = (const float*)d_in[1];
    const float* mu_b = (const float*)d_in[2];
    const float* lv_b = (const float*)d_in[3];
    float* out = (float*)d_out;

    pool_kernel<<<dim3(HP, CCH, 4), 256>>>(mu_a, lv_a, mu_b, lv_b);
    pair_kernel<<<dim3(NTILES, NDCH), 256>>>(out);
}